// round 2
// baseline (speedup 1.0000x reference)
#include <cuda_runtime.h>

// Problem constants
#define B_  64
#define T_  256
#define E_  512
#define U_  1024
#define N3_ 3072

#define NBLK 128          // scan grid (<=148 SMs, all resident -> barrier safe)
#define UPB  8            // GRU units per scan block (128*8 = 1024)
#define SCAN_THREADS 384  // 12 warps: 12 colgroups x 32 row-pairs
#define SCAN_SMEM (1024*24*8 + 64*64*4 + 24*64*4 + 32*4)  // whs2 + hc + recs + bhs

typedef unsigned long long u64;

// ----------------- device scratch (no allocations allowed) -----------------
__device__ float g_xproj[(size_t)B_ * T_ * N3_];  // [B*T][3U] incl. bx
__device__ float g_hT[2][U_ * B_];                // transposed h, double buffered
__device__ unsigned g_bar;

// ----------------- packed f32x2 helpers ------------------------------------
__device__ __forceinline__ u64 pack2(float lo, float hi) {
    u64 r;
    asm("mov.b64 %0, {%1, %2};" : "=l"(r)
        : "r"(__float_as_uint(lo)), "r"(__float_as_uint(hi)));
    return r;
}
__device__ __forceinline__ void unpack2(u64 v, float& lo, float& hi) {
    unsigned a, b;
    asm("mov.b64 {%0, %1}, %2;" : "=r"(a), "=r"(b) : "l"(v));
    lo = __uint_as_float(a);
    hi = __uint_as_float(b);
}
__device__ __forceinline__ u64 fma2(u64 a, u64 b, u64 c) {
    u64 d;
    asm("fma.rn.f32x2 %0, %1, %2, %3;" : "=l"(d) : "l"(a), "l"(b), "l"(c));
    return d;
}

// ----------------- init: reset barrier + transpose h0 ----------------------
__global__ void k_init(const float* __restrict__ hidden) {
    int idx = blockIdx.x * blockDim.x + threadIdx.x;
    if (idx == 0) g_bar = 0u;
    if (idx < B_ * U_) {
        int m = idx >> 10;        // batch row
        int k = idx & (U_ - 1);   // unit
        g_hT[0][k * B_ + m] = hidden[idx];
    }
}

// ----------------- kernel 1: x_proj = emb[tokens] @ Wx + bx ----------------
// 128x128 tile, KB=16, 256 threads, 8x8 micro via f32x2.
__global__ __launch_bounds__(256, 2)
void k_xproj(const int* __restrict__ tokens, const float* __restrict__ emb,
             const float* __restrict__ Wx, const float* __restrict__ bx) {
    __shared__ float As[16][132];   // [k][row] (A transposed)
    __shared__ float Bs[16][132];   // [k][col]
    __shared__ int toks[128];

    const int tid = threadIdx.x;
    const int n0 = blockIdx.x * 128;
    const int m0 = blockIdx.y * 128;

    if (tid < 128) toks[tid] = tokens[m0 + tid];

    const int tx = tid & 15;   // col group: cols tx*4..+3 and 64+tx*4..+3
    const int ty = tid >> 4;   // row group: rows ty*4..+3 and 64+ty*4..+3

    u64 acc[4][8];
#pragma unroll
    for (int g = 0; g < 4; g++)
#pragma unroll
        for (int j = 0; j < 8; j++) acc[g][j] = 0ull;

    for (int k0 = 0; k0 < E_; k0 += 16) {
        __syncthreads();
        // load A tile: 128 rows x 16 k, gathered through embedding
#pragma unroll
        for (int q0 = 0; q0 < 2; q0++) {
            int q = tid + q0 * 256;            // 0..511 float4s
            int row = q >> 2;
            int kb = (q & 3) << 2;
            const float4 av = *reinterpret_cast<const float4*>(
                &emb[(size_t)toks[row] * E_ + k0 + kb]);
            As[kb + 0][row] = av.x;
            As[kb + 1][row] = av.y;
            As[kb + 2][row] = av.z;
            As[kb + 3][row] = av.w;
        }
        // load B tile: 16 k x 128 cols
#pragma unroll
        for (int q0 = 0; q0 < 2; q0++) {
            int q = tid + q0 * 256;
            int kr = q >> 5;
            int nb = (q & 31) << 2;
            *reinterpret_cast<float4*>(&Bs[kr][nb]) =
                *reinterpret_cast<const float4*>(
                    &Wx[(size_t)(k0 + kr) * N3_ + n0 + nb]);
        }
        __syncthreads();

#pragma unroll
        for (int k = 0; k < 16; k++) {
            ulonglong2 a0 = *reinterpret_cast<const ulonglong2*>(&As[k][ty * 4]);
            ulonglong2 a1 = *reinterpret_cast<const ulonglong2*>(&As[k][64 + ty * 4]);
            float4 b0 = *reinterpret_cast<const float4*>(&Bs[k][tx * 4]);
            float4 b1 = *reinterpret_cast<const float4*>(&Bs[k][64 + tx * 4]);
            u64 ap[4] = {a0.x, a0.y, a1.x, a1.y};
            float bc[8] = {b0.x, b0.y, b0.z, b0.w, b1.x, b1.y, b1.z, b1.w};
#pragma unroll
            for (int j = 0; j < 8; j++) {
                u64 bp = pack2(bc[j], bc[j]);
#pragma unroll
                for (int g = 0; g < 4; g++) acc[g][j] = fma2(ap[g], bp, acc[g][j]);
            }
        }
    }

    // epilogue: add bias, store
    float bxv[8];
#pragma unroll
    for (int j = 0; j < 8; j++)
        bxv[j] = bx[n0 + ((j >> 2) ? 64 : 0) + tx * 4 + (j & 3)];

#pragma unroll
    for (int g = 0; g < 4; g++) {
        int r0 = ((g >> 1) << 6) + ty * 4 + ((g & 1) << 1);  // rows r0, r0+1
        float lo[8], hi[8];
#pragma unroll
        for (int j = 0; j < 8; j++) unpack2(acc[g][j], lo[j], hi[j]);
        float* p0 = &g_xproj[(size_t)(m0 + r0) * N3_ + n0];
        float* p1 = p0 + N3_;
        float4 v;
        v.x = lo[0] + bxv[0]; v.y = lo[1] + bxv[1];
        v.z = lo[2] + bxv[2]; v.w = lo[3] + bxv[3];
        *reinterpret_cast<float4*>(p0 + tx * 4) = v;
        v.x = lo[4] + bxv[4]; v.y = lo[5] + bxv[5];
        v.z = lo[6] + bxv[6]; v.w = lo[7] + bxv[7];
        *reinterpret_cast<float4*>(p0 + 64 + tx * 4) = v;
        v.x = hi[0] + bxv[0]; v.y = hi[1] + bxv[1];
        v.z = hi[2] + bxv[2]; v.w = hi[3] + bxv[3];
        *reinterpret_cast<float4*>(p1 + tx * 4) = v;
        v.x = hi[4] + bxv[4]; v.y = hi[5] + bxv[5];
        v.z = hi[6] + bxv[6]; v.w = hi[7] + bxv[7];
        *reinterpret_cast<float4*>(p1 + 64 + tx * 4) = v;
    }
}

// ----------------- kernel 2: persistent GRU scan ---------------------------
__global__ __launch_bounds__(SCAN_THREADS, 1)
void k_scan(const float* __restrict__ Wh, const float* __restrict__ bh,
            float* __restrict__ out) {
    extern __shared__ char smem[];
    u64* whs2 = reinterpret_cast<u64*>(smem);                      // [1024][24] (w,w)
    float* hc = reinterpret_cast<float*>(smem + 1024 * 24 * 8);    // [64][64]
    float* recs = hc + 64 * 64;                                    // [24][64]
    float* bhs = recs + 24 * 64;                                   // [24]

    const int tid = threadIdx.x;
    const int u0 = blockIdx.x * UPB;

    // stage Wh columns for this block's 8 units (z, r, hh triples), duplicated
    for (int idx = tid; idx < 1024 * 24; idx += SCAN_THREADS) {
        int k = idx / 24, j = idx % 24;
        int col = (j >> 3) * U_ + u0 + (j & 7);
        float w = Wh[(size_t)k * N3_ + col];
        whs2[idx] = pack2(w, w);
    }
    if (tid < 24) {
        int col = (tid >> 3) * U_ + u0 + (tid & 7);
        bhs[tid] = bh[col];
    }
    __syncthreads();

    const int rp = tid & 31;   // row pair: rows 2rp, 2rp+1
    const int cg = tid >> 5;   // 0..11
    const int c0 = cg * 2;     // 2 local cols per thread

    float4 pf[3];

    for (int t = 0; t < T_; t++) {
        const int buf = t & 1;
        const float* hsrc = g_hT[buf];
        float* hdst = g_hT[buf ^ 1];

        u64 acc0 = 0ull, acc1 = 0ull;

        // prefetch h chunk 0 (k = 0..63) into registers
#pragma unroll
        for (int j = 0; j < 3; j++) {
            int q = tid + j * SCAN_THREADS;
            if (q < 1024) {
                int k = q >> 4, c4 = (q & 15) << 2;
                pf[j] = __ldcg(reinterpret_cast<const float4*>(&hsrc[k * B_ + c4]));
            }
        }

        for (int ch = 0; ch < 16; ch++) {
            __syncthreads();  // previous chunk's readers are done with hc
#pragma unroll
            for (int j = 0; j < 3; j++) {
                int q = tid + j * SCAN_THREADS;
                if (q < 1024) {
                    int k = q >> 4, c4 = (q & 15) << 2;
                    *reinterpret_cast<float4*>(&hc[k * B_ + c4]) = pf[j];
                }
            }
            if (ch < 15) {
                int k0n = (ch + 1) * 64;
#pragma unroll
                for (int j = 0; j < 3; j++) {
                    int q = tid + j * SCAN_THREADS;
                    if (q < 1024) {
                        int k = q >> 4, c4 = (q & 15) << 2;
                        pf[j] = __ldcg(reinterpret_cast<const float4*>(
                            &hsrc[(k0n + k) * B_ + c4]));
                    }
                }
            }
            __syncthreads();

            const u64* wb = whs2 + (size_t)(ch * 64) * 24 + c0;
            const float* hb = hc + rp * 2;
#pragma unroll
            for (int kk = 0; kk < 64; kk++) {
                u64 hp = *reinterpret_cast<const u64*>(hb + kk * B_);
                ulonglong2 wv = *reinterpret_cast<const ulonglong2*>(wb + kk * 24);
                acc0 = fma2(hp, wv.x, acc0);
                acc1 = fma2(hp, wv.y, acc1);
            }
        }

        // write rec results (+bias) to smem
        {
            float l0, h0v, l1, h1v;
            unpack2(acc0, l0, h0v);
            unpack2(acc1, l1, h1v);
            float b0v = bhs[c0], b1v = bhs[c0 + 1];
            recs[c0 * B_ + rp * 2] = l0 + b0v;
            recs[c0 * B_ + rp * 2 + 1] = h0v + b0v;
            recs[(c0 + 1) * B_ + rp * 2] = l1 + b1v;
            recs[(c0 + 1) * B_ + rp * 2 + 1] = h1v + b1v;
        }
        __syncthreads();

        // gates: 64 rows x 8 units
        for (int o = tid; o < B_ * UPB; o += SCAN_THREADS) {
            int row = o >> 3, uu = o & 7;
            const float* xp = &g_xproj[((size_t)row * T_ + t) * N3_ + u0 + uu];
            float xz = xp[0], xr = xp[U_], xh = xp[2 * U_];
            float rz = recs[uu * B_ + row];
            float rr = recs[(8 + uu) * B_ + row];
            float rh = recs[(16 + uu) * B_ + row];
            float z = 1.f / (1.f + __expf(-(xz + rz)));
            float r = 1.f / (1.f + __expf(-(xr + rr)));
            float ca = xh + r * rh;
            float cand = 1.f - 2.f / (__expf(2.f * ca) + 1.f);
            int hidx = (u0 + uu) * B_ + row;
            float hold = __ldcg(&hsrc[hidx]);
            float hnew = z * hold + (1.f - z) * cand;
            __stcg(&hdst[hidx], hnew);
            out[((size_t)row * T_ + t) * U_ + u0 + uu] = hnew;
            if (t == T_ - 1)
                out[(size_t)B_ * T_ * U_ + (size_t)row * U_ + u0 + uu] = hnew;
        }

        // grid barrier (monotonic counter, all 128 blocks resident)
        __threadfence();
        __syncthreads();
        if (tid == 0) {
            atomicAdd(&g_bar, 1u);
            unsigned target = (unsigned)(NBLK * (t + 1));
            while (*((volatile unsigned*)&g_bar) < target) { }
        }
        __syncthreads();
    }
}

// ----------------- launch ---------------------------------------------------
extern "C" void kernel_launch(void* const* d_in, const int* in_sizes, int n_in,
                              void* d_out, int out_size) {
    const int* tokens = (const int*)d_in[0];
    const float* hidden = (const float*)d_in[1];
    const float* emb = (const float*)d_in[2];
    const float* Wx = (const float*)d_in[3];
    const float* bx = (const float*)d_in[4];
    const float* Wh = (const float*)d_in[5];
    const float* bh = (const float*)d_in[6];
    float* out = (float*)d_out;
    (void)in_sizes; (void)n_in; (void)out_size;

    cudaFuncSetAttribute(k_scan, cudaFuncAttributeMaxDynamicSharedMemorySize,
                         SCAN_SMEM);

    k_init<<<(B_ * U_ + 255) / 256, 256>>>(hidden);
    dim3 gx(N3_ / 128, (B_ * T_) / 128);
    k_xproj<<<gx, 256>>>(tokens, emb, Wx, bx);
    k_scan<<<NBLK, SCAN_THREADS, SCAN_SMEM>>>(Wh, bh, out);
}